// round 16
// baseline (speedup 1.0000x reference)
#include <cuda_runtime.h>

// Problem dims
#define B_   256
#define T_   32
#define IN_  2312
#define H_   1024
#define OUT_ 10
#define BH   (B_ * H_)

// LIF constants
#define DT_TAUMEM 0.05f
#define DT_TAUSYN 0.2f

// Device-global scratch
__device__ float g_inp1[(long)T_ * BH];   // x_t @ W1^T + b1, [t][b][h]
__device__ float g_w2t[(long)H_ * H_];    // W2 transposed: [k][h]

__device__ __forceinline__ void lif_update(float& v, float& cur, float inp, float& s) {
    float vd = v + DT_TAUMEM * (cur - v);
    float id = cur - DT_TAUSYN * cur;
    s = (vd - 1.0f) > 0.0f ? 1.0f : 0.0f;
    v = (1.0f - s) * vd;
    cur = id + inp;
}

// ---- packed f32x2 helpers (FFMA2 path, used by gemm1) ----------------------
__device__ __forceinline__ unsigned long long dup2(float x) {
    unsigned long long r;
    asm("mov.b64 %0, {%1, %1};" : "=l"(r) : "f"(x));
    return r;
}
__device__ __forceinline__ void fma2(unsigned long long& d,
                                     unsigned long long a, unsigned long long b) {
    asm("fma.rn.f32x2 %0, %1, %2, %0;" : "+l"(d) : "l"(a), "l"(b));
}
__device__ __forceinline__ float2 up2(unsigned long long v) {
    float2 f;
    asm("mov.b64 {%0, %1}, %2;" : "=f"(f.x), "=f"(f.y) : "l"(v));
    return f;
}

// ---------------------------------------------------------------------------
// W2 transpose: g_w2t[k][h] = W2[h][k]
// ---------------------------------------------------------------------------
__global__ void transpose_kernel(const float* __restrict__ W2) {
    __shared__ float tile[32][33];
    int x = blockIdx.x * 32 + threadIdx.x;   // k
    int y0 = blockIdx.y * 32;                // h
#pragma unroll
    for (int i = threadIdx.y; i < 32; i += 8)
        tile[i][threadIdx.x] = W2[(long)(y0 + i) * H_ + x];
    __syncthreads();
    int xo = blockIdx.y * 32 + threadIdx.x;  // h
    int yo = blockIdx.x * 32;                // k
#pragma unroll
    for (int i = threadIdx.y; i < 32; i += 8)
        g_w2t[(long)(yo + i) * H_ + xo] = tile[threadIdx.x][i];
}

// ---------------------------------------------------------------------------
// GEMM1: g_inp1[t][b][h] = x[m=b*32+t,:] . W1[h,:] + b1[h]
// Tile 64x128 (1024 blocks: finer quantum -> 1.2% SM imbalance vs 15%),
// BK=8, 256 thr, 4x8/thread, FFMA2. Inner issue mix identical to 128x128.
// ---------------------------------------------------------------------------
#define G1_BK 8
#define G1_APAD 68
#define G1_PAD 132
__global__ void __launch_bounds__(256) gemm1_kernel(
    const float* __restrict__ x, const float* __restrict__ W1,
    const float* __restrict__ b1)
{
    __shared__ float As[2][G1_BK][G1_APAD];   // 64 A rows
    __shared__ float Bs[2][G1_BK][G1_PAD];    // 128 B rows

    int tid = threadIdx.x;
    int m0 = blockIdx.y * 64;
    int n0 = blockIdx.x * 128;

    int lrow = tid >> 1;            // 0..127 (B rows; A uses 0..63 via tid<128)
    int lk4  = (tid & 1) * 4;       // 0 or 4
    const float* aptr = x  + (long)(m0 + lrow) * IN_ + lk4;   // valid for tid<128
    const float* bptr = W1 + (long)(n0 + lrow) * IN_ + lk4;

    int tx = tid & 15;              // col group (8 cols)
    int ty = tid >> 4;              // row group (4 rows), 0..15

    unsigned long long acc[4][4];
#pragma unroll
    for (int r = 0; r < 4; r++)
#pragma unroll
        for (int c = 0; c < 4; c++) acc[r][c] = 0ULL;

    float4 ra, rb;
    rb = *(const float4*)bptr;
    if (tid < 128) ra = *(const float4*)aptr;
#pragma unroll
    for (int i = 0; i < 4; i++) {
        Bs[0][lk4 + i][lrow] = ((const float*)&rb)[i];
        if (tid < 128) As[0][lk4 + i][lrow] = ((const float*)&ra)[i];
    }
    __syncthreads();

    const int nIter = IN_ / G1_BK;  // 289
    for (int it = 0; it < nIter; it++) {
        int cur = it & 1, nxt = cur ^ 1;
        if (it + 1 < nIter) {
            rb = *(const float4*)(bptr + (long)(it + 1) * G1_BK);
            if (tid < 128) ra = *(const float4*)(aptr + (long)(it + 1) * G1_BK);
        }
#pragma unroll
        for (int k = 0; k < G1_BK; k++) {
            float4 a0 = *(const float4*)&As[cur][k][ty * 4];
            ulonglong2 b01 = *(const ulonglong2*)&Bs[cur][k][tx * 4];
            ulonglong2 b23 = *(const ulonglong2*)&Bs[cur][k][tx * 4 + 64];
            unsigned long long ap[4], bp[4];
            ap[0] = dup2(a0.x); ap[1] = dup2(a0.y); ap[2] = dup2(a0.z); ap[3] = dup2(a0.w);
            bp[0] = b01.x; bp[1] = b01.y; bp[2] = b23.x; bp[3] = b23.y;
#pragma unroll
            for (int r = 0; r < 4; r++)
#pragma unroll
                for (int c = 0; c < 4; c++) fma2(acc[r][c], ap[r], bp[c]);
        }
        if (it + 1 < nIter) {
#pragma unroll
            for (int i = 0; i < 4; i++) {
                Bs[nxt][lk4 + i][lrow] = ((const float*)&rb)[i];
                if (tid < 128) As[nxt][lk4 + i][lrow] = ((const float*)&ra)[i];
            }
        }
        __syncthreads();
    }

#pragma unroll
    for (int r = 0; r < 4; r++) {
        int m = m0 + ty * 4 + r;
        int b = m >> 5;
        int t = m & 31;
        long orow = ((long)t * B_ + b) * H_;
#pragma unroll
        for (int c = 0; c < 4; c++) {
            int h = n0 + tx * 4 + (c & 1) * 2 + (c >> 1) * 64;
            float2 v = up2(acc[r][c]);
            g_inp1[orow + h]     = v.x + b1[h];
            g_inp1[orow + h + 1] = v.y + b1[h + 1];
        }
    }
}

// ---------------------------------------------------------------------------
// Persistent per-batch recurrence: block = one batch, 512 threads (2 h each),
// all T steps. Sparse GEMM2 via W2^T row accumulation, 8-deep unroll.
// (fp-exact: adds of 0.0 skipped, k-ascending order preserved)
// ---------------------------------------------------------------------------
__global__ void __launch_bounds__(512) batch_kernel(
    const float* __restrict__ Wout, const float* __restrict__ b2,
    const float* __restrict__ bout, float* __restrict__ out)
{
    __shared__ float s2s[H_];
    __shared__ int   acts[H_];
    __shared__ int   warp_cnt[16], warp_base[16], tot_s;
    __shared__ float vo_s[OUT_], io_s[OUT_], oacc[OUT_];

    int b = blockIdx.x;
    int tid = threadIdx.x;
    int wid = tid >> 5, lane = tid & 31;
    int h0 = tid * 2;

    if (tid < OUT_) { vo_s[tid] = 0.f; io_s[tid] = 0.f; oacc[tid] = 0.f; }

    float2 v1 = make_float2(0.f, 0.f), i1 = v1;
    float2 v2 = v1, i2 = v1;
    float2 b2r = *(const float2*)&b2[h0];
    const float2* W2T2 = (const float2*)g_w2t;
    const float* inp_base = g_inp1 + (long)b * H_ + h0;
    __syncthreads();

    for (int t = 0; t < T_; t++) {
        // ---- layer-1 LIF (2 neurons/thread) ----
        float2 inp = __ldg((const float2*)(inp_base + (long)t * BH));
        float2 s;
        lif_update(v1.x, i1.x, inp.x, s.x);
        lif_update(v1.y, i1.y, inp.y, s.y);

        // ---- deterministic k-ordered compaction of active spikes ----
        int c0 = s.x > 0.5f, c1 = s.y > 0.5f;
        int cnt = c0 + c1;
        int incl = cnt;
#pragma unroll
        for (int off = 1; off < 32; off <<= 1) {
            int n = __shfl_up_sync(0xffffffff, incl, off);
            if (lane >= off) incl += n;
        }
        if (lane == 31) warp_cnt[wid] = incl;
        __syncthreads();
        if (tid == 0) {
            int run = 0;
#pragma unroll
            for (int w = 0; w < 16; w++) { warp_base[w] = run; run += warp_cnt[w]; }
            tot_s = run;
        }
        __syncthreads();
        int p = warp_base[wid] + incl - cnt;
        if (c0) acts[p++] = h0;
        if (c1) acts[p++] = h0 + 1;
        __syncthreads();
        int tot = tot_s;

        // ---- sparse GEMM2: acc = b2 + sum_{active k} W2T[k][h0..h0+1] ----
        float2 acc = b2r;
        int i = 0;
        for (; i + 8 <= tot; i += 8) {
            float2 w0 = __ldg(&W2T2[(long)acts[i]     * 512 + tid]);
            float2 w1 = __ldg(&W2T2[(long)acts[i + 1] * 512 + tid]);
            float2 w2 = __ldg(&W2T2[(long)acts[i + 2] * 512 + tid]);
            float2 w3 = __ldg(&W2T2[(long)acts[i + 3] * 512 + tid]);
            float2 w4 = __ldg(&W2T2[(long)acts[i + 4] * 512 + tid]);
            float2 w5 = __ldg(&W2T2[(long)acts[i + 5] * 512 + tid]);
            float2 w6 = __ldg(&W2T2[(long)acts[i + 6] * 512 + tid]);
            float2 w7 = __ldg(&W2T2[(long)acts[i + 7] * 512 + tid]);
            acc.x += w0.x; acc.y += w0.y;
            acc.x += w1.x; acc.y += w1.y;
            acc.x += w2.x; acc.y += w2.y;
            acc.x += w3.x; acc.y += w3.y;
            acc.x += w4.x; acc.y += w4.y;
            acc.x += w5.x; acc.y += w5.y;
            acc.x += w6.x; acc.y += w6.y;
            acc.x += w7.x; acc.y += w7.y;
        }
        for (; i < tot; i++) {
            float2 w0 = __ldg(&W2T2[(long)acts[i] * 512 + tid]);
            acc.x += w0.x; acc.y += w0.y;
        }

        // ---- layer-2 LIF -> s2 in smem ----
        float2 s2;
        lif_update(v2.x, i2.x, acc.x, s2.x);
        lif_update(v2.y, i2.y, acc.y, s2.y);
        *(float2*)&s2s[h0] = s2;
        __syncthreads();

        // ---- output GEMV + LIF-out + rate accumulate (10 warps, 1 pass) ----
        if (wid < OUT_) {
            int o = wid;
            float sum = 0.f;
            const float* wrow = Wout + o * H_;
#pragma unroll 8
            for (int j = lane; j < H_; j += 32)
                sum = fmaf(s2s[j], __ldg(&wrow[j]), sum);
#pragma unroll
            for (int off = 16; off; off >>= 1)
                sum += __shfl_xor_sync(0xffffffff, sum, off);
            if (lane == 0) {
                float v = vo_s[o], cur = io_s[o], so;
                lif_update(v, cur, sum + bout[o], so);
                vo_s[o] = v; io_s[o] = cur;
                oacc[o] += so;
            }
        }
        __syncthreads();   // protect s2s/acts reuse next step
    }

    if (tid < OUT_) out[b * OUT_ + tid] = oacc[tid];
}

// ---------------------------------------------------------------------------
extern "C" void kernel_launch(void* const* d_in, const int* in_sizes, int n_in,
                              void* d_out, int out_size)
{
    const float* x    = (const float*)d_in[0];
    const float* W1   = (const float*)d_in[1];
    const float* b1   = (const float*)d_in[2];
    const float* W2   = (const float*)d_in[3];
    const float* b2   = (const float*)d_in[4];
    const float* Wout = (const float*)d_in[5];
    const float* bout = (const float*)d_in[6];
    float* out = (float*)d_out;

    // W2 transpose (for coalesced sparse row accumulation)
    transpose_kernel<<<dim3(H_ / 32, H_ / 32), dim3(32, 8)>>>(W2);

    // Time-parallel input GEMM (FFMA2, 64x128 tiles, 1024 blocks)
    gemm1_kernel<<<dim3(H_ / 128, (B_ * T_) / 64), 256>>>(x, W1, b1);

    // Entire recurrence: one persistent per-batch kernel
    batch_kernel<<<B_, 512>>>(Wout, b2, bout, out);
}

// round 17
// speedup vs baseline: 1.2474x; 1.2474x over previous
#include <cuda_runtime.h>

// Problem dims
#define B_   256
#define T_   32
#define IN_  2312
#define H_   1024
#define OUT_ 10
#define BH   (B_ * H_)

// LIF constants
#define DT_TAUMEM 0.05f
#define DT_TAUSYN 0.2f

// K split for gemm1: 2312 = 1160 + 1152 (both multiples of 8)
#define KSPLIT0 1160

// Device-global scratch
__device__ float g_inp1[(long)T_ * BH];   // K-chunk 0 partial (+bias), [t][b][h]
__device__ float g_inp2[(long)T_ * BH];   // K-chunk 1 partial,          [t][b][h]
__device__ float g_w2t[(long)H_ * H_];    // W2 transposed: [k][h]

__device__ __forceinline__ void lif_update(float& v, float& cur, float inp, float& s) {
    float vd = v + DT_TAUMEM * (cur - v);
    float id = cur - DT_TAUSYN * cur;
    s = (vd - 1.0f) > 0.0f ? 1.0f : 0.0f;
    v = (1.0f - s) * vd;
    cur = id + inp;
}

// ---- packed f32x2 helpers (FFMA2 path, used by gemm1) ----------------------
__device__ __forceinline__ unsigned long long dup2(float x) {
    unsigned long long r;
    asm("mov.b64 %0, {%1, %1};" : "=l"(r) : "f"(x));
    return r;
}
__device__ __forceinline__ void fma2(unsigned long long& d,
                                     unsigned long long a, unsigned long long b) {
    asm("fma.rn.f32x2 %0, %1, %2, %0;" : "+l"(d) : "l"(a), "l"(b));
}
__device__ __forceinline__ float2 up2(unsigned long long v) {
    float2 f;
    asm("mov.b64 {%0, %1}, %2;" : "=f"(f.x), "=f"(f.y) : "l"(v));
    return f;
}

// ---------------------------------------------------------------------------
// W2 transpose: g_w2t[k][h] = W2[h][k]
// ---------------------------------------------------------------------------
__global__ void transpose_kernel(const float* __restrict__ W2) {
    __shared__ float tile[32][33];
    int x = blockIdx.x * 32 + threadIdx.x;   // k
    int y0 = blockIdx.y * 32;                // h
#pragma unroll
    for (int i = threadIdx.y; i < 32; i += 8)
        tile[i][threadIdx.x] = W2[(long)(y0 + i) * H_ + x];
    __syncthreads();
    int xo = blockIdx.y * 32 + threadIdx.x;  // h
    int yo = blockIdx.x * 32;                // k
#pragma unroll
    for (int i = threadIdx.y; i < 32; i += 8)
        g_w2t[(long)(yo + i) * H_ + xo] = tile[threadIdx.x][i];
}

// ---------------------------------------------------------------------------
// GEMM1 split-K: 128x128 tile (R15-proven inner loop), BK=8, 256 thr,
// 8x8/thread, FFMA2. blockIdx.z selects K-chunk; 1024 half-quanta balance
// the SM schedule (busiest SM 3.5q vs 4q).
// ---------------------------------------------------------------------------
#define G1_BK 8
#define G1_PAD 132
__global__ void __launch_bounds__(256) gemm1_kernel(
    const float* __restrict__ x, const float* __restrict__ W1,
    const float* __restrict__ b1)
{
    __shared__ float As[2][G1_BK][G1_PAD];
    __shared__ float Bs[2][G1_BK][G1_PAD];

    int tid = threadIdx.x;
    int m0 = blockIdx.y * 128;
    int n0 = blockIdx.x * 128;
    int z  = blockIdx.z;
    int k0 = z ? KSPLIT0 : 0;
    const int nIter = (z ? (IN_ - KSPLIT0) : KSPLIT0) / G1_BK;  // 144 or 145

    int lrow = tid >> 1;
    int lk4  = (tid & 1) * 4;
    const float* aptr = x  + (long)(m0 + lrow) * IN_ + k0 + lk4;
    const float* bptr = W1 + (long)(n0 + lrow) * IN_ + k0 + lk4;

    int tx = tid & 15;
    int ty = tid >> 4;

    unsigned long long acc[8][4];
#pragma unroll
    for (int r = 0; r < 8; r++)
#pragma unroll
        for (int c = 0; c < 4; c++) acc[r][c] = 0ULL;

    float4 ra = *(const float4*)aptr;
    float4 rb = *(const float4*)bptr;
#pragma unroll
    for (int i = 0; i < 4; i++) {
        As[0][lk4 + i][lrow] = ((const float*)&ra)[i];
        Bs[0][lk4 + i][lrow] = ((const float*)&rb)[i];
    }
    __syncthreads();

    for (int it = 0; it < nIter; it++) {
        int cur = it & 1, nxt = cur ^ 1;
        if (it + 1 < nIter) {
            ra = *(const float4*)(aptr + (long)(it + 1) * G1_BK);
            rb = *(const float4*)(bptr + (long)(it + 1) * G1_BK);
        }
#pragma unroll
        for (int k = 0; k < G1_BK; k++) {
            float4 a0 = *(const float4*)&As[cur][k][ty * 4];
            float4 a1 = *(const float4*)&As[cur][k][ty * 4 + 64];
            ulonglong2 b01 = *(const ulonglong2*)&Bs[cur][k][tx * 4];
            ulonglong2 b23 = *(const ulonglong2*)&Bs[cur][k][tx * 4 + 64];
            unsigned long long ap[8], bp[4];
            ap[0] = dup2(a0.x); ap[1] = dup2(a0.y); ap[2] = dup2(a0.z); ap[3] = dup2(a0.w);
            ap[4] = dup2(a1.x); ap[5] = dup2(a1.y); ap[6] = dup2(a1.z); ap[7] = dup2(a1.w);
            bp[0] = b01.x; bp[1] = b01.y; bp[2] = b23.x; bp[3] = b23.y;
#pragma unroll
            for (int r = 0; r < 8; r++)
#pragma unroll
                for (int c = 0; c < 4; c++) fma2(acc[r][c], ap[r], bp[c]);
        }
        if (it + 1 < nIter) {
#pragma unroll
            for (int i = 0; i < 4; i++) {
                As[nxt][lk4 + i][lrow] = ((const float*)&ra)[i];
                Bs[nxt][lk4 + i][lrow] = ((const float*)&rb)[i];
            }
        }
        __syncthreads();
    }

    float* outp = z ? g_inp2 : g_inp1;
#pragma unroll
    for (int r = 0; r < 8; r++) {
        int m = m0 + ty * 4 + (r & 3) + (r >> 2) * 64;
        int b = m >> 5;
        int t = m & 31;
        long orow = ((long)t * B_ + b) * H_;
#pragma unroll
        for (int c = 0; c < 4; c++) {
            int h = n0 + tx * 4 + (c & 1) * 2 + (c >> 1) * 64;
            float2 v = up2(acc[r][c]);
            float bx = z ? 0.f : b1[h];
            float by = z ? 0.f : b1[h + 1];
            outp[orow + h]     = v.x + bx;
            outp[orow + h + 1] = v.y + by;
        }
    }
}

// ---------------------------------------------------------------------------
// Persistent per-batch recurrence: block = one batch, 512 threads (2 h each),
// all T steps. Layer-1 input = inp1 + inp2 (split-K partials).
// Sparse GEMM2 via W2^T row accumulation, 8-deep unroll.
// ---------------------------------------------------------------------------
__global__ void __launch_bounds__(512) batch_kernel(
    const float* __restrict__ Wout, const float* __restrict__ b2,
    const float* __restrict__ bout, float* __restrict__ out)
{
    __shared__ float s2s[H_];
    __shared__ int   acts[H_];
    __shared__ int   warp_cnt[16], warp_base[16], tot_s;
    __shared__ float vo_s[OUT_], io_s[OUT_], oacc[OUT_];

    int b = blockIdx.x;
    int tid = threadIdx.x;
    int wid = tid >> 5, lane = tid & 31;
    int h0 = tid * 2;

    if (tid < OUT_) { vo_s[tid] = 0.f; io_s[tid] = 0.f; oacc[tid] = 0.f; }

    float2 v1 = make_float2(0.f, 0.f), i1 = v1;
    float2 v2 = v1, i2 = v1;
    float2 b2r = *(const float2*)&b2[h0];
    const float2* W2T2 = (const float2*)g_w2t;
    long ib = (long)b * H_ + h0;
    __syncthreads();

    for (int t = 0; t < T_; t++) {
        // ---- layer-1 LIF (2 neurons/thread); input = sum of K-partials ----
        long ofs = (long)t * BH + ib;
        float2 p1 = __ldg((const float2*)&g_inp1[ofs]);
        float2 p2 = __ldg((const float2*)&g_inp2[ofs]);
        float2 inp = make_float2(p1.x + p2.x, p1.y + p2.y);
        float2 s;
        lif_update(v1.x, i1.x, inp.x, s.x);
        lif_update(v1.y, i1.y, inp.y, s.y);

        // ---- deterministic k-ordered compaction of active spikes ----
        int c0 = s.x > 0.5f, c1 = s.y > 0.5f;
        int cnt = c0 + c1;
        int incl = cnt;
#pragma unroll
        for (int off = 1; off < 32; off <<= 1) {
            int n = __shfl_up_sync(0xffffffff, incl, off);
            if (lane >= off) incl += n;
        }
        if (lane == 31) warp_cnt[wid] = incl;
        __syncthreads();
        if (tid == 0) {
            int run = 0;
#pragma unroll
            for (int w = 0; w < 16; w++) { warp_base[w] = run; run += warp_cnt[w]; }
            tot_s = run;
        }
        __syncthreads();
        int p = warp_base[wid] + incl - cnt;
        if (c0) acts[p++] = h0;
        if (c1) acts[p++] = h0 + 1;
        __syncthreads();
        int tot = tot_s;

        // ---- sparse GEMM2: acc = b2 + sum_{active k} W2T[k][h0..h0+1] ----
        float2 acc = b2r;
        int i = 0;
        for (; i + 8 <= tot; i += 8) {
            float2 w0 = __ldg(&W2T2[(long)acts[i]     * 512 + tid]);
            float2 w1 = __ldg(&W2T2[(long)acts[i + 1] * 512 + tid]);
            float2 w2 = __ldg(&W2T2[(long)acts[i + 2] * 512 + tid]);
            float2 w3 = __ldg(&W2T2[(long)acts[i + 3] * 512 + tid]);
            float2 w4 = __ldg(&W2T2[(long)acts[i + 4] * 512 + tid]);
            float2 w5 = __ldg(&W2T2[(long)acts[i + 5] * 512 + tid]);
            float2 w6 = __ldg(&W2T2[(long)acts[i + 6] * 512 + tid]);
            float2 w7 = __ldg(&W2T2[(long)acts[i + 7] * 512 + tid]);
            acc.x += w0.x; acc.y += w0.y;
            acc.x += w1.x; acc.y += w1.y;
            acc.x += w2.x; acc.y += w2.y;
            acc.x += w3.x; acc.y += w3.y;
            acc.x += w4.x; acc.y += w4.y;
            acc.x += w5.x; acc.y += w5.y;
            acc.x += w6.x; acc.y += w6.y;
            acc.x += w7.x; acc.y += w7.y;
        }
        for (; i < tot; i++) {
            float2 w0 = __ldg(&W2T2[(long)acts[i] * 512 + tid]);
            acc.x += w0.x; acc.y += w0.y;
        }

        // ---- layer-2 LIF -> s2 in smem ----
        float2 s2;
        lif_update(v2.x, i2.x, acc.x, s2.x);
        lif_update(v2.y, i2.y, acc.y, s2.y);
        *(float2*)&s2s[h0] = s2;
        __syncthreads();

        // ---- output GEMV + LIF-out + rate accumulate (10 warps, 1 pass) ----
        if (wid < OUT_) {
            int o = wid;
            float sum = 0.f;
            const float* wrow = Wout + o * H_;
#pragma unroll 8
            for (int j = lane; j < H_; j += 32)
                sum = fmaf(s2s[j], __ldg(&wrow[j]), sum);
#pragma unroll
            for (int off = 16; off; off >>= 1)
                sum += __shfl_xor_sync(0xffffffff, sum, off);
            if (lane == 0) {
                float v = vo_s[o], cur = io_s[o], so;
                lif_update(v, cur, sum + bout[o], so);
                vo_s[o] = v; io_s[o] = cur;
                oacc[o] += so;
            }
        }
        __syncthreads();   // protect s2s/acts reuse next step
    }

    if (tid < OUT_) out[b * OUT_ + tid] = oacc[tid];
}

// ---------------------------------------------------------------------------
extern "C" void kernel_launch(void* const* d_in, const int* in_sizes, int n_in,
                              void* d_out, int out_size)
{
    const float* x    = (const float*)d_in[0];
    const float* W1   = (const float*)d_in[1];
    const float* b1   = (const float*)d_in[2];
    const float* W2   = (const float*)d_in[3];
    const float* b2   = (const float*)d_in[4];
    const float* Wout = (const float*)d_in[5];
    const float* bout = (const float*)d_in[6];
    float* out = (float*)d_out;

    // W2 transpose (for coalesced sparse row accumulation)
    transpose_kernel<<<dim3(H_ / 32, H_ / 32), dim3(32, 8)>>>(W2);

    // Time-parallel input GEMM (FFMA2, 128x128 tiles, split-K z=2 -> 1024 blocks)
    gemm1_kernel<<<dim3(H_ / 128, (B_ * T_) / 128, 2), 256>>>(x, W1, b1);

    // Entire recurrence: one persistent per-batch kernel
    batch_kernel<<<B_, 512>>>(Wout, b2, bout, out);
}